// round 6
// baseline (speedup 1.0000x reference)
#include <cuda_runtime.h>
#include <math.h>

#define BB 32
#define NN 1000
#define BN (BB*NN)
#define DD 64
#define HID 256
#define OBS 147
#define KSEL 500
#define NEGV (-1e8f)
#define NIT 16          // i-tiles of 64
#define NJC 4           // j-chunks of 256

// ---------------- scratch (device globals; no allocation) ----------------
__device__ float g_x[(size_t)BN*15];
__device__ float g_h4[(size_t)BB*256*64*4];       // [b][j>>2][d][j&3], pads j>=1000 unused (p=0)
__device__ float g_hs[BN];
__device__ float g_hd[BN];
__device__ float g_comp[(size_t)BN*DD];
__device__ float g_coop[(size_t)BN*DD];
__device__ float g_pacc[(size_t)BB*NIT*NJC*4096];
__device__ float g_spart[(size_t)BB*NIT*NJC*64];
__device__ float g_xp[(size_t)BN*HID];
__device__ float g_scores[2*BN];
__device__ float g_w[2*BN];
__device__ float g_pp[2*BB*4*2*HID];
__device__ int   g_flag4;

// ---------------- f32x2 helpers ----------------
__device__ __forceinline__ unsigned long long pk2(float a, float b) {
    unsigned long long r;
    asm("mov.b64 %0, {%1,%2};" : "=l"(r) : "f"(a), "f"(b));
    return r;
}
__device__ __forceinline__ void upk2(unsigned long long v, float& a, float& b) {
    asm("mov.b64 {%0,%1}, %2;" : "=f"(a), "=f"(b) : "l"(v));
}
__device__ __forceinline__ unsigned long long ffma2(unsigned long long a, unsigned long long b,
                                                    unsigned long long c) {
    unsigned long long d;
    asm("fma.rn.f32x2 %0, %1, %2, %3;" : "=l"(d) : "l"(a), "l"(b), "l"(c));
    return d;
}

// ---------------- bool-width detection ----------------
__global__ void detect_kernel(const unsigned char* p, int nbytes) {
    __shared__ int any;
    if (threadIdx.x == 0) any = 0;
    __syncthreads();
    int loc = 0;
    for (int i = threadIdx.x; i < nbytes; i += blockDim.x)
        if ((i & 3) && p[i]) loc = 1;
    if (loc) any = 1;
    __syncthreads();
    if (threadIdx.x == 0) g_flag4 = any ? 0 : 1;
}

__device__ __forceinline__ bool bget(const void* p, size_t idx, int f4) {
    return f4 ? (((const int*)p)[idx] != 0) : (((const unsigned char*)p)[idx] != 0);
}

// ---------------- x = [cs(4), tp(2), vf(9)] ----------------
__global__ void buildx_kernel(const int* __restrict__ op_idx, const float* __restrict__ vf,
                              const float* __restrict__ cs_tab, const float* __restrict__ tp_tab) {
    int idx = blockIdx.x * blockDim.x + threadIdx.x;
    if (idx >= BN) return;
    int n = idx % NN;
    float* xr = g_x + (size_t)idx * 15;
    int op = op_idx[idx];
#pragma unroll
    for (int c = 0; c < 4; c++) xr[c] = cs_tab[n * 4 + c];
    xr[4] = tp_tab[op * 2 + 0];
    xr[5] = tp_tab[op * 2 + 1];
#pragma unroll
    for (int c = 0; c < 9; c++) xr[6 + c] = vf[(size_t)idx * 9 + c];
}

// ---------------- h = x @ W (quad-packed out), hd, hs ----------------
__global__ __launch_bounds__(256) void h_kernel(const float* __restrict__ xa, int Fa,
                                                const float* __restrict__ xb, int Fb,
                                                const float* __restrict__ W,
                                                const float* __restrict__ asrc,
                                                const float* __restrict__ adst) {
    __shared__ float xs[4][80];
    __shared__ float red[4][2][2];
    int nl = threadIdx.x >> 6, d = threadIdx.x & 63;
    size_t gn = (size_t)blockIdx.x * 4 + nl;
    for (int f = d; f < Fa; f += 64) xs[nl][f] = xa[gn * Fa + f];
    for (int f = d; f < Fb; f += 64) xs[nl][Fa + f] = xb[gn * Fb + f];
    __syncthreads();
    int F = Fa + Fb;
    float acc = 0.f;
    for (int f = 0; f < F; f++) acc = fmaf(xs[nl][f], W[f * DD + d], acc);
    int b = (int)(gn / NN), j = (int)(gn - (size_t)b * NN);
    g_h4[(((size_t)b * 256 + (j >> 2)) * 64 + d) * 4 + (j & 3)] = acc;
    float p1 = acc * adst[d], p2 = acc * asrc[d];
    for (int o = 16; o; o >>= 1) {
        p1 += __shfl_xor_sync(0xffffffffu, p1, o);
        p2 += __shfl_xor_sync(0xffffffffu, p2, o);
    }
    if ((d & 31) == 0) { red[nl][d >> 5][0] = p1; red[nl][d >> 5][1] = p2; }
    __syncthreads();
    if (threadIdx.x < 4) {
        size_t g2 = (size_t)blockIdx.x * 4 + threadIdx.x;
        g_hd[g2] = red[threadIdx.x][0][0] + red[threadIdx.x][1][0];
        g_hs[g2] = red[threadIdx.x][0][1] + red[threadIdx.x][1][1];
    }
}

// ---------------- fused GAT partial: (b, i-tile 64, j-chunk 256) ----------------
// p-phase: thread = (one j, 16 consecutive i) -> coalesced adj/dist.
// MMA: warp = 8 dst, lane = dims (lane, lane+32); j-quad LDS.128 everywhere.
__global__ __launch_bounds__(256, 3) void gat_kernel(const float* __restrict__ wdp,
                                                     const void* __restrict__ adj,
                                                     const float* __restrict__ dist) {
    const float wd = *wdp;
    const int f4 = g_flag4;
    const int it = blockIdx.x, jc = blockIdx.y, b = blockIdx.z;
    const int iG0 = it * 64, jbase = jc * 256;
    const int t = threadIdx.x, w = t >> 5, lane = t & 31;
    const int pidx = (b * NJC + jc) * NIT + it;

    __shared__ unsigned long long p_pair[64][34];   // floats: [i][j] at i*68+j
    __shared__ ulonglong2 h2[16][64];               // [q][d]: j 4q..4q+3
    __shared__ float hd_s[64];
    __shared__ float hs_s[256];

    const int j_loc = t & 63, i_seg = t >> 6, i0s = i_seg * 16;
    if (t < 64) { int iG = iG0 + t; hd_s[t] = (iG < NN) ? g_hd[b * NN + iG] : 0.f; }
    { int jG = jbase + t; hs_s[t] = (jG < NN) ? g_hs[b * NN + jG] : 0.f; }

    const int nvalidI = NN - iG0;
    const bool fastI = (i0s + 16 <= nvalidI);
    const bool rawB = (!f4) && fastI;

    float ps[16];
#pragma unroll
    for (int k = 0; k < 16; k++) ps[k] = 0.f;

    unsigned long long acc[8][2];
#pragma unroll
    for (int g = 0; g < 8; g++) { acc[g][0] = 0ull; acc[g][1] = 0ull; }
    const int iw = w * 8;

    const unsigned char* ab = (const unsigned char*)adj;
    const int* ai32 = (const int*)adj;

    float dv[16];
    unsigned long long a64[2] = {0ull, 0ull};
    bool jv_c = false;

#define LOADTILE(stv) do {                                                          \
    int jG = jbase + (stv) * 64 + j_loc;                                            \
    jv_c = (jG < NN);                                                               \
    if (jv_c) {                                                                     \
        if (fastI) {                                                                \
            size_t off = (size_t)b * NN * NN + (size_t)jG * NN + (iG0 + i0s);       \
            if (!f4) {                                                              \
                const unsigned long long* pa = (const unsigned long long*)(ab + off);\
                a64[0] = __ldg(pa); a64[1] = __ldg(pa + 1);                         \
            } else {                                                                \
                const int4* pi = (const int4*)(ai32 + off);                         \
                int4 q0 = __ldg(pi), q1 = __ldg(pi+1), q2 = __ldg(pi+2), q3 = __ldg(pi+3); \
                unsigned m = 0;                                                     \
                m |= (q0.x?1u:0u)|(q0.y?2u:0u)|(q0.z?4u:0u)|(q0.w?8u:0u);           \
                m |= (q1.x?16u:0u)|(q1.y?32u:0u)|(q1.z?64u:0u)|(q1.w?128u:0u);      \
                m |= (q2.x?256u:0u)|(q2.y?512u:0u)|(q2.z?1024u:0u)|(q2.w?2048u:0u); \
                m |= (q3.x?4096u:0u)|(q3.y?8192u:0u)|(q3.z?16384u:0u)|(q3.w?32768u:0u); \
                a64[0] = m;                                                         \
            }                                                                       \
            const float4* pd = (const float4*)(dist + (size_t)jG * NN + (iG0 + i0s)); \
            float4 d0 = __ldg(pd), d1 = __ldg(pd+1), d2 = __ldg(pd+2), d3 = __ldg(pd+3); \
            dv[0]=d0.x; dv[1]=d0.y; dv[2]=d0.z; dv[3]=d0.w;                         \
            dv[4]=d1.x; dv[5]=d1.y; dv[6]=d1.z; dv[7]=d1.w;                         \
            dv[8]=d2.x; dv[9]=d2.y; dv[10]=d2.z; dv[11]=d2.w;                       \
            dv[12]=d3.x; dv[13]=d3.y; dv[14]=d3.z; dv[15]=d3.w;                     \
        } else {                                                                    \
            unsigned m = 0;                                                         \
            _Pragma("unroll")                                                       \
            for (int k = 0; k < 16; k++) {                                          \
                int iG = iG0 + i0s + k; dv[k] = 0.f;                                \
                if (iG < NN) {                                                      \
                    size_t idx = (size_t)b * NN * NN + (size_t)jG * NN + iG;        \
                    int av = f4 ? ai32[idx] : (int)ab[idx];                         \
                    if (av) m |= 1u << k;                                           \
                    dv[k] = __ldg(&dist[(size_t)jG * NN + iG]);                     \
                }                                                                   \
            }                                                                       \
            a64[0] = m;                                                             \
        }                                                                           \
    }                                                                               \
} while (0)

    LOADTILE(0);
    const float4* hbase4 = ((const float4*)g_h4) + (size_t)(b * 256 + jc * 64) * 64;

    for (int st = 0; st < 4; st++) {
        // ---- fill h2 (flat copy, quad-packed in global) ----
        {
            const float4* hsrc = hbase4 + (size_t)st * 1024;
            float4* hdst = (float4*)h2;
            hdst[t]       = __ldg(hsrc + t);
            hdst[t + 256] = __ldg(hsrc + t + 256);
            hdst[t + 512] = __ldg(hsrc + t + 512);
            hdst[t + 768] = __ldg(hsrc + t + 768);
        }
        // ---- compute p from prefetched regs ----
        {
            unsigned msk = 0;
            if (jv_c) {
                if (rawB) {
                    unsigned long long x0 = a64[0], x1 = a64[1];
#pragma unroll
                    for (int k = 0; k < 8; k++) {
                        if ((x0 >> (8 * k)) & 0xFFull) msk |= 1u << k;
                        if ((x1 >> (8 * k)) & 0xFFull) msk |= 1u << (k + 8);
                    }
                } else msk = (unsigned)a64[0];
            }
            float hsv = hs_s[st * 64 + j_loc];
            float* prow = (float*)p_pair;
#pragma unroll
            for (int k = 0; k < 16; k++) {
                float p = 0.f;
                if (msk & (1u << k)) {
                    float ev = hd_s[i0s + k] + hsv + wd * dv[k];
                    ev = (ev >= 0.f) ? ev : 0.2f * ev;
                    p = __expf(ev);
                }
                prow[(i0s + k) * 68 + j_loc] = p;
                ps[k] += p;
            }
        }
        // ---- prefetch next subtile (overlaps MMA) ----
        if (st < 3) LOADTILE(st + 1);
        __syncthreads();
        // ---- MMA ----
#pragma unroll 4
        for (int q = 0; q < 16; q++) {
            ulonglong2 ha = h2[q][lane];
            ulonglong2 hb = h2[q][lane + 32];
#pragma unroll
            for (int g = 0; g < 8; g++) {
                ulonglong2 pq = *(const ulonglong2*)&p_pair[iw + g][2 * q];
                acc[g][0] = ffma2(pq.x, ha.x, acc[g][0]);
                acc[g][0] = ffma2(pq.y, ha.y, acc[g][0]);
                acc[g][1] = ffma2(pq.x, hb.x, acc[g][1]);
                acc[g][1] = ffma2(pq.y, hb.y, acc[g][1]);
            }
        }
        __syncthreads();
    }
#undef LOADTILE

    // ---- s reduction: reuse p_pair memory, stride 67 (odd, conflict-free) ----
    {
        float* srf = (float*)p_pair;
#pragma unroll
        for (int k = 0; k < 16; k++) srf[(i0s + k) * 67 + j_loc] = ps[k];
        __syncthreads();
        if (t < 64) {
            float s = 0.f;
            for (int jl = 0; jl < 64; jl++) s += srf[t * 67 + jl];
            g_spart[(size_t)pidx * 64 + t] = s;
        }
    }
    // ---- store partial acc ----
    float* pw = g_pacc + (size_t)pidx * 4096;
#pragma unroll
    for (int g = 0; g < 8; g++) {
        float a0, a1, b0, b1;
        upk2(acc[g][0], a0, a1);
        upk2(acc[g][1], b0, b1);
        int il = iw + g;
        pw[il * 64 + lane] = a0 + a1;
        pw[il * 64 + lane + 32] = b0 + b1;
    }
}

// ---------------- GAT finalize: reduce chunks, divide, elu ----------------
__global__ __launch_bounds__(256) void gat_fin_kernel(float* __restrict__ outrep) {
    int it = blockIdx.x, b = blockIdx.y;
    int t = threadIdx.x;
    __shared__ float s_tot[64];
    if (t < 64) {
        float s = 0.f;
#pragma unroll
        for (int jcc = 0; jcc < NJC; jcc++)
            s += g_spart[(size_t)((b * NJC + jcc) * NIT + it) * 64 + t];
        s_tot[t] = s;
    }
    __syncthreads();
#pragma unroll
    for (int e = 0; e < 16; e++) {
        int idx = t + e * 256;
        int il = idx >> 6, d = idx & 63;
        int ig = it * 64 + il;
        if (ig >= NN) continue;
        float a = 0.f;
#pragma unroll
        for (int jcc = 0; jcc < NJC; jcc++)
            a += g_pacc[(size_t)((b * NJC + jcc) * NIT + it) * 4096 + idx];
        float s = s_tot[il];
        float inv = (s > 0.f) ? 1.f / s : 0.f;
        float v = a * inv;
        v = (v > 0.f) ? v : expm1f(v);
        outrep[((size_t)b * NN + ig) * DD + d] = v;
    }
}

// ---------------- x_p = sag @ Wp + bp (32 nodes/block) ----------------
__global__ __launch_bounds__(256) void xp_kernel(const int* __restrict__ time_idx,
                                                 const int* __restrict__ op_idx,
                                                 const float* __restrict__ vf,
                                                 const float* __restrict__ time_tab,
                                                 const float* __restrict__ cs_tab,
                                                 const float* __restrict__ tp_tab,
                                                 const float* __restrict__ Wp,
                                                 const float* __restrict__ bp,
                                                 float* __restrict__ xp) {
    __shared__ __align__(16) float sag[OBS][32];
    int t = threadIdx.x, w = t >> 5, lane = t & 31;
    size_t gn0 = (size_t)blockIdx.x * 32;
#pragma unroll
    for (int nl2 = 0; nl2 < 4; nl2++) {
        int node = w * 4 + nl2;
        size_t gn = gn0 + node;
        int n = (int)(gn % NN);
        int ti = time_idx[gn], op = op_idx[gn];
        for (int f = lane; f < OBS; f += 32) {
            float v;
            if (f < 4)       v = time_tab[ti * 4 + f];
            else if (f < 8)  v = cs_tab[n * 4 + (f - 4)];
            else if (f < 10) v = tp_tab[op * 2 + (f - 8)];
            else if (f < 19) v = vf[gn * 9 + (f - 10)];
            else if (f < 83) v = g_comp[gn * 64 + (f - 19)];
            else             v = g_coop[gn * 64 + (f - 83)];
            sag[f][node] = v;
        }
    }
    __syncthreads();
    int h = t;
    float bv = bp[h];
    unsigned long long acc2[16];
    unsigned long long bv2 = pk2(bv, bv);
#pragma unroll
    for (int k = 0; k < 16; k++) acc2[k] = bv2;
#pragma unroll 3
    for (int f = 0; f < OBS; f++) {
        float wv = Wp[f * HID + h];
        unsigned long long wv2 = pk2(wv, wv);
        const ulonglong2* sp = (const ulonglong2*)&sag[f][0];
#pragma unroll
        for (int k2 = 0; k2 < 8; k2++) {
            ulonglong2 s2 = sp[k2];
            acc2[2 * k2]     = ffma2(wv2, s2.x, acc2[2 * k2]);
            acc2[2 * k2 + 1] = ffma2(wv2, s2.y, acc2[2 * k2 + 1]);
        }
    }
#pragma unroll
    for (int k = 0; k < 16; k++) {
        float x0, x1;
        upk2(acc2[k], x0, x1);
        xp[(gn0 + 2 * k) * HID + h] = x0;
        xp[(gn0 + 2 * k + 1) * HID + h] = x1;
    }
}

// ---------------- scores = xp . vpd / vpf ----------------
__global__ void scores_kernel(const float* __restrict__ xp, const float* __restrict__ vpd,
                              const float* __restrict__ vpf) {
    int w = threadIdx.x >> 5, lane = threadIdx.x & 31;
    size_t gn = (size_t)blockIdx.x * 8 + w;
    const float* r = xp + gn * HID;
    float sd = 0.f, sf = 0.f;
#pragma unroll
    for (int k = 0; k < 8; k++) {
        int hh = lane + 32 * k;
        float v = r[hh];
        sd = fmaf(v, vpd[hh], sd);
        sf = fmaf(v, vpf[hh], sf);
    }
    for (int o = 16; o; o >>= 1) {
        sd += __shfl_xor_sync(0xffffffffu, sd, o);
        sf += __shfl_xor_sync(0xffffffffu, sf, o);
    }
    if (lane == 0) { g_scores[gn] = sf; g_scores[BN + gn] = sd; }
}

// ---------------- pooling: weights (sort + softmax) ----------------
__global__ __launch_bounds__(256) void pool_w_kernel(const void* __restrict__ dpcs) {
    int b = blockIdx.x, type = blockIdx.y;
    __shared__ float sc[1024];
    __shared__ float sraw[NN];
    __shared__ float red[256];
    int f4 = g_flag4;
    const float* srow = g_scores + (size_t)type * BN + (size_t)b * NN;

    float lm = -INFINITY;
    for (int n = threadIdx.x; n < NN; n += 256) lm = fmaxf(lm, srow[n]);
    red[threadIdx.x] = lm;
    __syncthreads();
    for (int o = 128; o; o >>= 1) {
        if (threadIdx.x < o) red[threadIdx.x] = fmaxf(red[threadIdx.x], red[threadIdx.x + o]);
        __syncthreads();
    }
    float gm = red[0];
    __syncthreads();

    for (int n = threadIdx.x; n < 1024; n += 256) {
        float v = -INFINITY;
        if (n < NN) {
            bool mk = bget(dpcs, (size_t)b * NN + n, f4);
            bool valid = type ? mk : !mk;
            float sv = valid ? (srow[n] - gm) : NEGV;
            sraw[n] = sv;
            v = sv;
        }
        sc[n] = v;
    }
    __syncthreads();

    for (int k = 2; k <= 1024; k <<= 1)
        for (int j = k >> 1; j > 0; j >>= 1) {
            for (int i = threadIdx.x; i < 1024; i += 256) {
                int ixj = i ^ j;
                if (ixj > i) {
                    float a = sc[i], c = sc[ixj];
                    bool dirAsc = (i & k) == 0;
                    bool sw = dirAsc ? (a < c) : (a > c);
                    if (sw) { sc[i] = c; sc[ixj] = a; }
                }
            }
            __syncthreads();
        }
    float th = sc[KSEL - 1];
    float mx = sc[0];

    float part = 0.f;
    for (int n = threadIdx.x; n < NN; n += 256) {
        float sv = sraw[n];
        float p = (sv >= th) ? __expf(sv - mx) : 0.f;
        sraw[n] = p;
        part += p;
    }
    __syncthreads();
    red[threadIdx.x] = part;
    __syncthreads();
    for (int o = 128; o; o >>= 1) {
        if (threadIdx.x < o) red[threadIdx.x] += red[threadIdx.x + o];
        __syncthreads();
    }
    float invS = 1.f / red[0];
    float* wrow = g_w + (size_t)type * BN + (size_t)b * NN;
    for (int n = threadIdx.x; n < NN; n += 256) wrow[n] = sraw[n] * invS;
}

// ---------------- pooling: partial weighted sum/max ----------------
__global__ __launch_bounds__(256) void pool_sum_kernel(const float* __restrict__ xp) {
    int b = blockIdx.x, type = blockIdx.y, q = blockIdx.z;
    int h = threadIdx.x;
    const float* wrow = g_w + (size_t)type * BN + (size_t)b * NN;
    const float* xpb = xp + (size_t)b * NN * HID + h;
    int n0 = q * 250, n1 = n0 + 250;
    float sum = 0.f, mxv = -INFINITY;
    for (int n = n0; n < n1; n++) {
        float xv = wrow[n] * xpb[(size_t)n * HID];
        sum += xv;
        mxv = fmaxf(mxv, xv);
    }
    float* pp = g_pp + ((((size_t)type * BB + b) * 4 + q) * 2) * HID;
    pp[h] = sum;
    pp[HID + h] = mxv;
}

// ---------------- pooling: combine ----------------
__global__ void pool_fin_kernel(float* __restrict__ out) {
    int b = blockIdx.x, type = blockIdx.y;
    int h = threadIdx.x;
    float sum = 0.f, mxv = -INFINITY;
#pragma unroll
    for (int q = 0; q < 4; q++) {
        const float* pp = g_pp + ((((size_t)type * BB + b) * 4 + q) * 2) * HID;
        sum += pp[h];
        mxv = fmaxf(mxv, pp[HID + h]);
    }
    float* ob = out + (size_t)b * 1024 + type * 512;
    ob[h] = sum;
    ob[256 + h] = mxv;
}

// ---------------- launch ----------------
extern "C" void kernel_launch(void* const* d_in, const int* in_sizes, int n_in,
                              void* d_out, int out_size) {
    const int*   time_idx = (const int*)d_in[0];
    const int*   op_idx   = (const int*)d_in[1];
    const float* vf       = (const float*)d_in[2];
    const void*  dpcs     = d_in[3];
    const void*  adjc     = d_in[4];
    const void*  adjo     = d_in[5];
    const float* dist     = (const float*)d_in[6];
    const float* time_tab = (const float*)d_in[7];
    const float* tp_tab   = (const float*)d_in[8];
    const float* cs_tab   = (const float*)d_in[9];
    const float* Wc       = (const float*)d_in[10];
    const float* asrc_c   = (const float*)d_in[11];
    const float* adst_c   = (const float*)d_in[12];
    const float* wd_c     = (const float*)d_in[13];
    const float* Wco      = (const float*)d_in[14];
    const float* asrc_co  = (const float*)d_in[15];
    const float* adst_co  = (const float*)d_in[16];
    const float* wd_co    = (const float*)d_in[17];
    const float* Wp       = (const float*)d_in[18];
    const float* bp       = (const float*)d_in[19];
    const float* vpd      = (const float*)d_in[20];
    const float* vpf      = (const float*)d_in[21];
    float* out = (float*)d_out;

    float *px, *pcomp, *pcoop, *pxp;
    cudaGetSymbolAddress((void**)&px,    g_x);
    cudaGetSymbolAddress((void**)&pcomp, g_comp);
    cudaGetSymbolAddress((void**)&pcoop, g_coop);
    cudaGetSymbolAddress((void**)&pxp,   g_xp);

    detect_kernel<<<1, 256>>>((const unsigned char*)adjc, 32000);
    buildx_kernel<<<BN / 256 + 1, 256>>>(op_idx, vf, cs_tab, tp_tab);

    h_kernel<<<BN / 4, 256>>>(px, 15, (const float*)nullptr, 0, Wc, asrc_c, adst_c);
    gat_kernel<<<dim3(NIT, NJC, BB), 256>>>(wd_c, adjc, dist);
    gat_fin_kernel<<<dim3(NIT, BB), 256>>>(pcomp);

    h_kernel<<<BN / 4, 256>>>(px, 15, pcomp, 64, Wco, asrc_co, adst_co);
    gat_kernel<<<dim3(NIT, NJC, BB), 256>>>(wd_co, adjo, dist);
    gat_fin_kernel<<<dim3(NIT, BB), 256>>>(pcoop);

    xp_kernel<<<BN / 32, 256>>>(time_idx, op_idx, vf, time_tab, cs_tab, tp_tab, Wp, bp, pxp);
    scores_kernel<<<BN / 8, 256>>>(pxp, vpd, vpf);
    pool_w_kernel<<<dim3(BB, 2), 256>>>(dpcs);
    pool_sum_kernel<<<dim3(BB, 2, 4), 256>>>(pxp);
    pool_fin_kernel<<<dim3(BB, 2), 256>>>(out);
}

// round 7
// speedup vs baseline: 1.0518x; 1.0518x over previous
#include <cuda_runtime.h>
#include <math.h>

#define BB 32
#define NN 1000
#define BN (BB*NN)
#define DD 64
#define HID 256
#define OBS 147
#define KSEL 500
#define NEGV (-1e8f)
#define NIT 16          // i-tiles of 64
#define NJC 4           // j-chunks of 256

// ---------------- scratch (device globals; no allocation) ----------------
__device__ float g_x[(size_t)BN*15];
__device__ float g_h4[(size_t)BB*256*64*4];       // [b][j>>2][d][j&3]
__device__ float g_hs[BN];
__device__ float g_hd[BN];
__device__ float g_comp[(size_t)BN*DD];
__device__ float g_coop[(size_t)BN*DD];
__device__ float g_pacc[(size_t)BB*NIT*NJC*4096];
__device__ float g_spart[(size_t)BB*NIT*NJC*64];
__device__ float g_xp[(size_t)BN*HID];
__device__ float g_scores[2*BN];
__device__ float g_w[2*BN];
__device__ float g_pp[2*BB*4*2*HID];
__device__ int   g_flag4;

// ---------------- f32x2 helpers ----------------
__device__ __forceinline__ unsigned long long pk2(float a, float b) {
    unsigned long long r;
    asm("mov.b64 %0, {%1,%2};" : "=l"(r) : "f"(a), "f"(b));
    return r;
}
__device__ __forceinline__ void upk2(unsigned long long v, float& a, float& b) {
    asm("mov.b64 {%0,%1}, %2;" : "=f"(a), "=f"(b) : "l"(v));
}
__device__ __forceinline__ unsigned long long ffma2(unsigned long long a, unsigned long long b,
                                                    unsigned long long c) {
    unsigned long long d;
    asm("fma.rn.f32x2 %0, %1, %2, %3;" : "=l"(d) : "l"(a), "l"(b), "l"(c));
    return d;
}

// ---------------- bool-width detection ----------------
__global__ void detect_kernel(const unsigned char* p, int nbytes) {
    __shared__ int any;
    if (threadIdx.x == 0) any = 0;
    __syncthreads();
    int loc = 0;
    for (int i = threadIdx.x; i < nbytes; i += blockDim.x)
        if ((i & 3) && p[i]) loc = 1;
    if (loc) any = 1;
    __syncthreads();
    if (threadIdx.x == 0) g_flag4 = any ? 0 : 1;
}

__device__ __forceinline__ bool bget(const void* p, size_t idx, int f4) {
    return f4 ? (((const int*)p)[idx] != 0) : (((const unsigned char*)p)[idx] != 0);
}

// ---------------- x = [cs(4), tp(2), vf(9)] ----------------
__global__ void buildx_kernel(const int* __restrict__ op_idx, const float* __restrict__ vf,
                              const float* __restrict__ cs_tab, const float* __restrict__ tp_tab) {
    int idx = blockIdx.x * blockDim.x + threadIdx.x;
    if (idx >= BN) return;
    int n = idx % NN;
    float* xr = g_x + (size_t)idx * 15;
    int op = op_idx[idx];
#pragma unroll
    for (int c = 0; c < 4; c++) xr[c] = cs_tab[n * 4 + c];
    xr[4] = tp_tab[op * 2 + 0];
    xr[5] = tp_tab[op * 2 + 1];
#pragma unroll
    for (int c = 0; c < 9; c++) xr[6 + c] = vf[(size_t)idx * 9 + c];
}

// ---------------- h = x @ W (quad-packed out), hd, hs ----------------
__global__ __launch_bounds__(256) void h_kernel(const float* __restrict__ xa, int Fa,
                                                const float* __restrict__ xb, int Fb,
                                                const float* __restrict__ W,
                                                const float* __restrict__ asrc,
                                                const float* __restrict__ adst) {
    __shared__ float xs[4][80];
    __shared__ float red[4][2][2];
    int nl = threadIdx.x >> 6, d = threadIdx.x & 63;
    size_t gn = (size_t)blockIdx.x * 4 + nl;
    for (int f = d; f < Fa; f += 64) xs[nl][f] = xa[gn * Fa + f];
    for (int f = d; f < Fb; f += 64) xs[nl][Fa + f] = xb[gn * Fb + f];
    __syncthreads();
    int F = Fa + Fb;
    float acc = 0.f;
    for (int f = 0; f < F; f++) acc = fmaf(xs[nl][f], W[f * DD + d], acc);
    int b = (int)(gn / NN), j = (int)(gn - (size_t)b * NN);
    g_h4[(((size_t)b * 256 + (j >> 2)) * 64 + d) * 4 + (j & 3)] = acc;
    float p1 = acc * adst[d], p2 = acc * asrc[d];
    for (int o = 16; o; o >>= 1) {
        p1 += __shfl_xor_sync(0xffffffffu, p1, o);
        p2 += __shfl_xor_sync(0xffffffffu, p2, o);
    }
    if ((d & 31) == 0) { red[nl][d >> 5][0] = p1; red[nl][d >> 5][1] = p2; }
    __syncthreads();
    if (threadIdx.x < 4) {
        size_t g2 = (size_t)blockIdx.x * 4 + threadIdx.x;
        g_hd[g2] = red[threadIdx.x][0][0] + red[threadIdx.x][1][0];
        g_hs[g2] = red[threadIdx.x][0][1] + red[threadIdx.x][1][1];
    }
}

// ---------------- fused GAT partial: (b, i-tile 64, j-chunk 256) ----------------
// p-phase (R5 assignment): thread = (one i, 16 consecutive j) -> lanes consecutive i
// => adj loads 1 sector/warp, dist 4 sectors/warp. p stored as j-quad ulonglong2
// with 17-pack row stride (conflict-free STS.128).
// MMA (R6 style): warp = 8 dst, lane = dims (lane, lane+32); LDS.128 h + LDS.128 p bcast.
__global__ __launch_bounds__(256, 3) void gat_kernel(const float* __restrict__ wdp,
                                                     const void* __restrict__ adj,
                                                     const float* __restrict__ dist) {
    const float wd = *wdp;
    const int f4 = g_flag4;
    const int it = blockIdx.x, jc = blockIdx.y, b = blockIdx.z;
    const int iG0 = it * 64, jbase = jc * 256;
    const int t = threadIdx.x, w = t >> 5, lane = t & 31;
    const int pidx = (b * NJC + jc) * NIT + it;

    __shared__ ulonglong2 p4[64][17];               // [i][j-quad], row 272B
    __shared__ ulonglong2 h2[16][64];               // [q][d]
    __shared__ float hs_s[256];
    __shared__ float s_part[4][64];

    const int i_loc = t & 63;
    const int qq = t >> 6;                          // owns j = qq*16 .. qq*16+15 in subtile
    const int iG = iG0 + i_loc;
    const bool ivalid = iG < NN;
    const float hdv = ivalid ? g_hd[b * NN + iG] : 0.f;
    float sacc = 0.f;

    { int jG = jbase + t; hs_s[t] = (jG < NN) ? g_hs[b * NN + jG] : 0.f; }

    const unsigned char* ab = (const unsigned char*)adj;
    const int mult = f4 ? 4 : 1;
    const size_t abyte = (size_t)b * NN * NN * mult;

    unsigned long long acc[8][2];
#pragma unroll
    for (int g = 0; g < 8; g++) { acc[g][0] = 0ull; acc[g][1] = 0ull; }
    const int iw = w * 8;

    unsigned char av[16];
    float dv[16];

#define LOADTILE(stv) do {                                                      \
    _Pragma("unroll")                                                           \
    for (int k = 0; k < 16; k++) {                                              \
        int jG = jbase + (stv) * 64 + qq * 16 + k;                              \
        bool ok = ivalid && (jG < NN);                                          \
        av[k] = ok ? ab[((size_t)jG * NN + iG) * mult + abyte] : 0;             \
        dv[k] = ok ? __ldg(&dist[(size_t)jG * NN + iG]) : 0.f;                  \
    }                                                                           \
} while (0)

    LOADTILE(0);
    const float4* hbase4 = ((const float4*)g_h4) + (size_t)(b * 256 + jc * 64) * 64;

    for (int st = 0; st < 4; st++) {
        // ---- fill h2 (flat coalesced copy, quad-packed in global) ----
        {
            const float4* hsrc = hbase4 + (size_t)st * 1024;
            float4* hdst = (float4*)h2;
            hdst[t]       = __ldg(hsrc + t);
            hdst[t + 256] = __ldg(hsrc + t + 256);
            hdst[t + 512] = __ldg(hsrc + t + 512);
            hdst[t + 768] = __ldg(hsrc + t + 768);
        }
        // ---- compute p, pack as j-quads ----
        {
            float pv0 = 0.f, pv1 = 0.f, pv2 = 0.f;
#pragma unroll
            for (int k = 0; k < 16; k++) {
                float p = 0.f;
                if (av[k]) {
                    float ev = hdv + hs_s[st * 64 + qq * 16 + k] + wd * dv[k];
                    ev = (ev >= 0.f) ? ev : 0.2f * ev;
                    p = __expf(ev);
                }
                sacc += p;
                int r = k & 3;
                if (r == 0) pv0 = p;
                else if (r == 1) pv1 = p;
                else if (r == 2) pv2 = p;
                else p4[i_loc][qq * 4 + (k >> 2)] = make_ulonglong2(pk2(pv0, pv1), pk2(pv2, p));
            }
        }
        // ---- prefetch next subtile (overlaps MMA) ----
        if (st < 3) LOADTILE(st + 1);
        __syncthreads();
        // ---- MMA ----
#pragma unroll 4
        for (int q = 0; q < 16; q++) {
            ulonglong2 ha = h2[q][lane];
            ulonglong2 hb = h2[q][lane + 32];
#pragma unroll
            for (int g = 0; g < 8; g++) {
                ulonglong2 pq = p4[iw + g][q];
                acc[g][0] = ffma2(pq.x, ha.x, acc[g][0]);
                acc[g][0] = ffma2(pq.y, ha.y, acc[g][0]);
                acc[g][1] = ffma2(pq.x, hb.x, acc[g][1]);
                acc[g][1] = ffma2(pq.y, hb.y, acc[g][1]);
            }
        }
        __syncthreads();
    }
#undef LOADTILE

    // ---- reduce s per dst ----
    s_part[qq][i_loc] = sacc;
    __syncthreads();
    if (t < 64)
        g_spart[(size_t)pidx * 64 + t] = s_part[0][t] + s_part[1][t] + s_part[2][t] + s_part[3][t];
    // ---- store partial acc ----
    float* pw = g_pacc + (size_t)pidx * 4096;
#pragma unroll
    for (int g = 0; g < 8; g++) {
        float a0, a1, b0, b1;
        upk2(acc[g][0], a0, a1);
        upk2(acc[g][1], b0, b1);
        int il = iw + g;
        pw[il * 64 + lane] = a0 + a1;
        pw[il * 64 + lane + 32] = b0 + b1;
    }
}

// ---------------- GAT finalize: reduce chunks, divide, elu ----------------
__global__ __launch_bounds__(256) void gat_fin_kernel(float* __restrict__ outrep) {
    int it = blockIdx.x, b = blockIdx.y;
    int t = threadIdx.x;
    __shared__ float s_tot[64];
    if (t < 64) {
        float s = 0.f;
#pragma unroll
        for (int jcc = 0; jcc < NJC; jcc++)
            s += g_spart[(size_t)((b * NJC + jcc) * NIT + it) * 64 + t];
        s_tot[t] = s;
    }
    __syncthreads();
#pragma unroll
    for (int e = 0; e < 16; e++) {
        int idx = t + e * 256;
        int il = idx >> 6, d = idx & 63;
        int ig = it * 64 + il;
        if (ig >= NN) continue;
        float a = 0.f;
#pragma unroll
        for (int jcc = 0; jcc < NJC; jcc++)
            a += g_pacc[(size_t)((b * NJC + jcc) * NIT + it) * 4096 + idx];
        float s = s_tot[il];
        float inv = (s > 0.f) ? 1.f / s : 0.f;
        float v = a * inv;
        v = (v > 0.f) ? v : expm1f(v);
        outrep[((size_t)b * NN + ig) * DD + d] = v;
    }
}

// ---------------- x_p = sag @ Wp + bp (32 nodes/block) ----------------
__global__ __launch_bounds__(256) void xp_kernel(const int* __restrict__ time_idx,
                                                 const int* __restrict__ op_idx,
                                                 const float* __restrict__ vf,
                                                 const float* __restrict__ time_tab,
                                                 const float* __restrict__ cs_tab,
                                                 const float* __restrict__ tp_tab,
                                                 const float* __restrict__ Wp,
                                                 const float* __restrict__ bp,
                                                 float* __restrict__ xp) {
    __shared__ __align__(16) float sag[OBS][32];
    int t = threadIdx.x, w = t >> 5, lane = t & 31;
    size_t gn0 = (size_t)blockIdx.x * 32;
#pragma unroll
    for (int nl2 = 0; nl2 < 4; nl2++) {
        int node = w * 4 + nl2;
        size_t gn = gn0 + node;
        int n = (int)(gn % NN);
        int ti = time_idx[gn], op = op_idx[gn];
        for (int f = lane; f < OBS; f += 32) {
            float v;
            if (f < 4)       v = time_tab[ti * 4 + f];
            else if (f < 8)  v = cs_tab[n * 4 + (f - 4)];
            else if (f < 10) v = tp_tab[op * 2 + (f - 8)];
            else if (f < 19) v = vf[gn * 9 + (f - 10)];
            else if (f < 83) v = g_comp[gn * 64 + (f - 19)];
            else             v = g_coop[gn * 64 + (f - 83)];
            sag[f][node] = v;
        }
    }
    __syncthreads();
    int h = t;
    float bv = bp[h];
    unsigned long long acc2[16];
    unsigned long long bv2 = pk2(bv, bv);
#pragma unroll
    for (int k = 0; k < 16; k++) acc2[k] = bv2;
#pragma unroll 3
    for (int f = 0; f < OBS; f++) {
        float wv = Wp[f * HID + h];
        unsigned long long wv2 = pk2(wv, wv);
        const ulonglong2* sp = (const ulonglong2*)&sag[f][0];
#pragma unroll
        for (int k2 = 0; k2 < 8; k2++) {
            ulonglong2 s2 = sp[k2];
            acc2[2 * k2]     = ffma2(wv2, s2.x, acc2[2 * k2]);
            acc2[2 * k2 + 1] = ffma2(wv2, s2.y, acc2[2 * k2 + 1]);
        }
    }
#pragma unroll
    for (int k = 0; k < 16; k++) {
        float x0, x1;
        upk2(acc2[k], x0, x1);
        xp[(gn0 + 2 * k) * HID + h] = x0;
        xp[(gn0 + 2 * k + 1) * HID + h] = x1;
    }
}

// ---------------- scores = xp . vpd / vpf ----------------
__global__ void scores_kernel(const float* __restrict__ xp, const float* __restrict__ vpd,
                              const float* __restrict__ vpf) {
    int w = threadIdx.x >> 5, lane = threadIdx.x & 31;
    size_t gn = (size_t)blockIdx.x * 8 + w;
    const float* r = xp + gn * HID;
    float sd = 0.f, sf = 0.f;
#pragma unroll
    for (int k = 0; k < 8; k++) {
        int hh = lane + 32 * k;
        float v = r[hh];
        sd = fmaf(v, vpd[hh], sd);
        sf = fmaf(v, vpf[hh], sf);
    }
    for (int o = 16; o; o >>= 1) {
        sd += __shfl_xor_sync(0xffffffffu, sd, o);
        sf += __shfl_xor_sync(0xffffffffu, sf, o);
    }
    if (lane == 0) { g_scores[gn] = sf; g_scores[BN + gn] = sd; }
}

// ---------------- pooling: weights (sort + softmax) ----------------
__global__ __launch_bounds__(256) void pool_w_kernel(const void* __restrict__ dpcs) {
    int b = blockIdx.x, type = blockIdx.y;
    __shared__ float sc[1024];
    __shared__ float sraw[NN];
    __shared__ float red[256];
    int f4 = g_flag4;
    const float* srow = g_scores + (size_t)type * BN + (size_t)b * NN;

    float lm = -INFINITY;
    for (int n = threadIdx.x; n < NN; n += 256) lm = fmaxf(lm, srow[n]);
    red[threadIdx.x] = lm;
    __syncthreads();
    for (int o = 128; o; o >>= 1) {
        if (threadIdx.x < o) red[threadIdx.x] = fmaxf(red[threadIdx.x], red[threadIdx.x + o]);
        __syncthreads();
    }
    float gm = red[0];
    __syncthreads();

    for (int n = threadIdx.x; n < 1024; n += 256) {
        float v = -INFINITY;
        if (n < NN) {
            bool mk = bget(dpcs, (size_t)b * NN + n, f4);
            bool valid = type ? mk : !mk;
            float sv = valid ? (srow[n] - gm) : NEGV;
            sraw[n] = sv;
            v = sv;
        }
        sc[n] = v;
    }
    __syncthreads();

    for (int k = 2; k <= 1024; k <<= 1)
        for (int j = k >> 1; j > 0; j >>= 1) {
            for (int i = threadIdx.x; i < 1024; i += 256) {
                int ixj = i ^ j;
                if (ixj > i) {
                    float a = sc[i], c = sc[ixj];
                    bool dirAsc = (i & k) == 0;
                    bool sw = dirAsc ? (a < c) : (a > c);
                    if (sw) { sc[i] = c; sc[ixj] = a; }
                }
            }
            __syncthreads();
        }
    float th = sc[KSEL - 1];
    float mx = sc[0];

    float part = 0.f;
    for (int n = threadIdx.x; n < NN; n += 256) {
        float sv = sraw[n];
        float p = (sv >= th) ? __expf(sv - mx) : 0.f;
        sraw[n] = p;
        part += p;
    }
    __syncthreads();
    red[threadIdx.x] = part;
    __syncthreads();
    for (int o = 128; o; o >>= 1) {
        if (threadIdx.x < o) red[threadIdx.x] += red[threadIdx.x + o];
        __syncthreads();
    }
    float invS = 1.f / red[0];
    float* wrow = g_w + (size_t)type * BN + (size_t)b * NN;
    for (int n = threadIdx.x; n < NN; n += 256) wrow[n] = sraw[n] * invS;
}

// ---------------- pooling: partial weighted sum/max ----------------
__global__ __launch_bounds__(256) void pool_sum_kernel(const float* __restrict__ xp) {
    int b = blockIdx.x, type = blockIdx.y, q = blockIdx.z;
    int h = threadIdx.x;
    const float* wrow = g_w + (size_t)type * BN + (size_t)b * NN;
    const float* xpb = xp + (size_t)b * NN * HID + h;
    int n0 = q * 250, n1 = n0 + 250;
    float sum = 0.f, mxv = -INFINITY;
    for (int n = n0; n < n1; n++) {
        float xv = wrow[n] * xpb[(size_t)n * HID];
        sum += xv;
        mxv = fmaxf(mxv, xv);
    }
    float* pp = g_pp + ((((size_t)type * BB + b) * 4 + q) * 2) * HID;
    pp[h] = sum;
    pp[HID + h] = mxv;
}

// ---------------- pooling: combine ----------------
__global__ void pool_fin_kernel(float* __restrict__ out) {
    int b = blockIdx.x, type = blockIdx.y;
    int h = threadIdx.x;
    float sum = 0.f, mxv = -INFINITY;
#pragma unroll
    for (int q = 0; q < 4; q++) {
        const float* pp = g_pp + ((((size_t)type * BB + b) * 4 + q) * 2) * HID;
        sum += pp[h];
        mxv = fmaxf(mxv, pp[HID + h]);
    }
    float* ob = out + (size_t)b * 1024 + type * 512;
    ob[h] = sum;
    ob[256 + h] = mxv;
}

// ---------------- launch ----------------
extern "C" void kernel_launch(void* const* d_in, const int* in_sizes, int n_in,
                              void* d_out, int out_size) {
    const int*   time_idx = (const int*)d_in[0];
    const int*   op_idx   = (const int*)d_in[1];
    const float* vf       = (const float*)d_in[2];
    const void*  dpcs     = d_in[3];
    const void*  adjc     = d_in[4];
    const void*  adjo     = d_in[5];
    const float* dist     = (const float*)d_in[6];
    const float* time_tab = (const float*)d_in[7];
    const float* tp_tab   = (const float*)d_in[8];
    const float* cs_tab   = (const float*)d_in[9];
    const float* Wc       = (const float*)d_in[10];
    const float* asrc_c   = (const float*)d_in[11];
    const float* adst_c   = (const float*)d_in[12];
    const float* wd_c     = (const float*)d_in[13];
    const float* Wco      = (const float*)d_in[14];
    const float* asrc_co  = (const float*)d_in[15];
    const float* adst_co  = (const float*)d_in[16];
    const float* wd_co    = (const float*)d_in[17];
    const float* Wp       = (const float*)d_in[18];
    const float* bp       = (const float*)d_in[19];
    const float* vpd      = (const float*)d_in[20];
    const float* vpf      = (const float*)d_in[21];
    float* out = (float*)d_out;

    float *px, *pcomp, *pcoop, *pxp;
    cudaGetSymbolAddress((void**)&px,    g_x);
    cudaGetSymbolAddress((void**)&pcomp, g_comp);
    cudaGetSymbolAddress((void**)&pcoop, g_coop);
    cudaGetSymbolAddress((void**)&pxp,   g_xp);

    detect_kernel<<<1, 256>>>((const unsigned char*)adjc, 32000);
    buildx_kernel<<<BN / 256 + 1, 256>>>(op_idx, vf, cs_tab, tp_tab);

    h_kernel<<<BN / 4, 256>>>(px, 15, (const float*)nullptr, 0, Wc, asrc_c, adst_c);
    gat_kernel<<<dim3(NIT, NJC, BB), 256>>>(wd_c, adjc, dist);
    gat_fin_kernel<<<dim3(NIT, BB), 256>>>(pcomp);

    h_kernel<<<BN / 4, 256>>>(px, 15, pcomp, 64, Wco, asrc_co, adst_co);
    gat_kernel<<<dim3(NIT, NJC, BB), 256>>>(wd_co, adjo, dist);
    gat_fin_kernel<<<dim3(NIT, BB), 256>>>(pcoop);

    xp_kernel<<<BN / 32, 256>>>(time_idx, op_idx, vf, time_tab, cs_tab, tp_tab, Wp, bp, pxp);
    scores_kernel<<<BN / 8, 256>>>(pxp, vpd, vpf);
    pool_w_kernel<<<dim3(BB, 2), 256>>>(dpcs);
    pool_sum_kernel<<<dim3(BB, 2, 4), 256>>>(pxp);
    pool_fin_kernel<<<dim3(BB, 2), 256>>>(out);
}